// round 1
// baseline (speedup 1.0000x reference)
#include <cuda_runtime.h>
#include <cstdint>

typedef long long ll;

#define BATCH 8192
#define INS   1024
#define GG    1024
#define HS    2048
#define KTOT  2048

#define BM 128
#define BN 128
#define BK 16
#define NKT (KTOT/BK)

// Scratch (static __device__ arrays — no runtime allocation allowed)
__device__ float g_HA[(size_t)BATCH * GG];   // h2_fl, later h1_fl
__device__ float g_HB[(size_t)BATCH * GG];   // r * h_fl
__device__ float g_Z [(size_t)BATCH * GG];   // z1, later z2
__device__ double g_bp1[1024];
__device__ double g_bp2[1024];

__device__ __forceinline__ uint32_t smaddr(const void* p) {
    return (uint32_t)__cvta_generic_to_shared(p);
}
__device__ __forceinline__ void cp16(uint32_t d, const void* s) {
    asm volatile("cp.async.cg.shared.global [%0], [%1], 16;\n" :: "r"(d), "l"(s));
}
__device__ __forceinline__ void cpcommit() { asm volatile("cp.async.commit_group;\n" ::); }
__device__ __forceinline__ void cpwait0()  { asm volatile("cp.async.wait_group 0;\n" ::); }

// m16n8k8 tf32 mma, accumulate in place. Raw fp32 bits fed as tf32 (HW truncates).
__device__ __forceinline__ void mma_tf32(float* d, const uint32_t* a, const uint32_t* b) {
    asm volatile(
        "mma.sync.aligned.m16n8k8.row.col.f32.tf32.tf32.f32 "
        "{%0,%1,%2,%3}, {%4,%5,%6,%7}, {%8,%9}, {%0,%1,%2,%3};\n"
        : "+f"(d[0]), "+f"(d[1]), "+f"(d[2]), "+f"(d[3])
        : "r"(a[0]), "r"(a[1]), "r"(a[2]), "r"(a[3]), "r"(b[0]), "r"(b[1]));
}

// EPI 0: zr GEMM (N=2048). cols < G: z = 0.875*sig+0.125 -> g_Z.
//                           cols >= G: r = sig; g_HB = r * g_HA.
// EPI 1: g GEMM (N=1024). g = tanh; fixed-point hidden update; writes
//        recurrent (as float), output_hidden, and optionally h_fl -> g_HA.
template<int EPI>
__global__ void __launch_bounds__(256, 2) gemm_k(
    const float* __restrict__ x,
    const float* __restrict__ W,
    const float* __restrict__ bias,
    int Ncols,
    int hinSel,                      // 0 = g_HA, 1 = g_HB for k >= 1024
    const int* __restrict__ hidden,  // EPI1 only
    int hoff,                        // EPI1: 0 (h1) or 1024 (h2)
    float* __restrict__ out,         // EPI1 only
    int writeHA)                     // EPI1 only
{
    __shared__ float As[2][BM][20];     // [m][k], pad to 20 (conflict-free frag loads)
    __shared__ float Bs[2][BK][136];    // [k][n], pad to 136

    const float* Hin = hinSel ? g_HB : g_HA;

    const int tid  = threadIdx.x;
    const int warp = tid >> 5, lane = tid & 31;
    const int wm0  = (warp >> 2) * 64;   // 2 warps in M
    const int wn0  = (warp & 3) * 32;    // 4 warps in N
    const int bm0  = blockIdx.y * BM;
    const int bn0  = blockIdx.x * BN;

    float acc[4][4][4];
    #pragma unroll
    for (int i = 0; i < 4; ++i)
        #pragma unroll
        for (int j = 0; j < 4; ++j)
            #pragma unroll
            for (int e = 0; e < 4; ++e)
                acc[i][j][e] = 0.0f;

    auto load_tile = [&](int kt, int buf) {
        int kbase = kt * BK;
        const float* abase = (kbase < INS) ? (x + kbase) : (Hin + (kbase - INS));
        #pragma unroll
        for (int it = 0; it < 2; ++it) {
            int q   = tid + it * 256;
            int row = q >> 2;
            int c4  = (q & 3) * 4;
            cp16(smaddr(&As[buf][row][c4]), abase + (size_t)(bm0 + row) * INS + c4);
        }
        #pragma unroll
        for (int it = 0; it < 2; ++it) {
            int q  = tid + it * 256;
            int kr = q >> 5;
            int n4 = (q & 31) * 4;
            cp16(smaddr(&Bs[buf][kr][n4]), W + (size_t)(kbase + kr) * Ncols + bn0 + n4);
        }
    };

    load_tile(0, 0); cpcommit(); cpwait0(); __syncthreads();

    const int rm = lane >> 2, ck = lane & 3;

    for (int kt = 0; kt < NKT; ++kt) {
        int buf = kt & 1;
        if (kt + 1 < NKT) { load_tile(kt + 1, buf ^ 1); cpcommit(); }

        #pragma unroll
        for (int ks = 0; ks < 2; ++ks) {
            int k0 = ks * 8;
            uint32_t af[4][4], bf[4][2];
            #pragma unroll
            for (int mi = 0; mi < 4; ++mi) {
                int m = wm0 + mi * 16 + rm;
                af[mi][0] = __float_as_uint(As[buf][m    ][k0 + ck    ]);
                af[mi][1] = __float_as_uint(As[buf][m + 8][k0 + ck    ]);
                af[mi][2] = __float_as_uint(As[buf][m    ][k0 + ck + 4]);
                af[mi][3] = __float_as_uint(As[buf][m + 8][k0 + ck + 4]);
            }
            #pragma unroll
            for (int ni = 0; ni < 4; ++ni) {
                int n = wn0 + ni * 8 + rm;
                bf[ni][0] = __float_as_uint(Bs[buf][k0 + ck    ][n]);
                bf[ni][1] = __float_as_uint(Bs[buf][k0 + ck + 4][n]);
            }
            #pragma unroll
            for (int mi = 0; mi < 4; ++mi)
                #pragma unroll
                for (int ni = 0; ni < 4; ++ni)
                    mma_tf32(acc[mi][ni], af[mi], bf[ni]);
        }
        cpwait0();
        __syncthreads();
    }

    // ---- epilogue ----
    const int c2 = (lane & 3) * 2;

    if (EPI == 0) {
        #pragma unroll
        for (int mi = 0; mi < 4; ++mi) {
            #pragma unroll
            for (int rr = 0; rr < 2; ++rr) {
                int m = bm0 + wm0 + mi * 16 + rm + rr * 8;
                #pragma unroll
                for (int ni = 0; ni < 4; ++ni) {
                    int n = bn0 + wn0 + ni * 8 + c2;
                    float v0 = acc[mi][ni][rr * 2 + 0] + bias[n];
                    float v1 = acc[mi][ni][rr * 2 + 1] + bias[n + 1];
                    float s0 = 1.0f / (1.0f + expf(-v0));
                    float s1 = 1.0f / (1.0f + expf(-v1));
                    if (n < GG) {
                        float2 z;
                        z.x = 0.875f * s0 + 0.125f;
                        z.y = 0.875f * s1 + 0.125f;
                        *(float2*)&g_Z[(size_t)m * GG + n] = z;
                    } else {
                        size_t j = (size_t)m * GG + (n - GG);
                        float2 ha = *(const float2*)&g_HA[j];
                        float2 hb;
                        hb.x = s0 * ha.x;
                        hb.y = s1 * ha.y;
                        *(float2*)&g_HB[j] = hb;
                    }
                }
            }
        }
    } else {
        #pragma unroll
        for (int mi = 0; mi < 4; ++mi) {
            #pragma unroll
            for (int rr = 0; rr < 2; ++rr) {
                int m = bm0 + wm0 + mi * 16 + rm + rr * 8;
                #pragma unroll
                for (int ni = 0; ni < 4; ++ni) {
                    int n = bn0 + wn0 + ni * 8 + c2;
                    size_t zj = (size_t)m * GG + n;
                    float2 zv = *(const float2*)&g_Z[zj];
                    int2  hv  = *(const int2*)&hidden[(size_t)m * HS + hoff + n];
                    float2 recf, ohf;
                    {
                        float gval = tanhf(acc[mi][ni][rr * 2 + 0] + bias[n]);
                        ll zf = (ll)(zv.x * 1024.0f); if (zf < 1) zf = 1;
                        ll hn = (((ll)hv.x * zf) >> 10)
                              + (ll)((1.0f - zv.x) * gval * 8388608.0f);
                        int hi = (int)hn;
                        recf.x = (float)hi;
                        ohf.x  = (float)hi * (1.0f / 8388608.0f);
                    }
                    {
                        float gval = tanhf(acc[mi][ni][rr * 2 + 1] + bias[n + 1]);
                        ll zf = (ll)(zv.y * 1024.0f); if (zf < 1) zf = 1;
                        ll hn = (((ll)hv.y * zf) >> 10)
                              + (ll)((1.0f - zv.y) * gval * 8388608.0f);
                        int hi = (int)hn;
                        recf.y = (float)hi;
                        ohf.y  = (float)hi * (1.0f / 8388608.0f);
                    }
                    *(float2*)&out[(size_t)m * HS + hoff + n] = recf;
                    *(float2*)&out[(size_t)BATCH * HS + (size_t)m * HS + hoff + n] = ohf;
                    if (writeHA) {
                        *(float2*)&g_HA[zj] = ohf;  // h1_fl for the second half
                    }
                }
            }
        }
    }
}

// HA = h2_fl = hidden[:, G:] / 2^23
__global__ void prep_k(const int* __restrict__ hidden) {
    size_t N = (size_t)BATCH * GG;
    for (size_t i = (size_t)blockIdx.x * blockDim.x + threadIdx.x; i < N;
         i += (size_t)gridDim.x * blockDim.x) {
        size_t row = i >> 10;
        int col = (int)(i & 1023);
        g_HA[i] = (float)hidden[row * HS + GG + col] * (1.0f / 8388608.0f);
    }
}

// Deterministic block-partial reduction of -log2(z) over g_Z.
__global__ void bits_k(const int* __restrict__ slice_ptr, int which) {
    int slice = slice_ptr ? __ldg(slice_ptr) : 0;
    double s = 0.0;
    size_t N = (size_t)BATCH * GG;
    for (size_t i = (size_t)blockIdx.x * blockDim.x + threadIdx.x; i < N;
         i += (size_t)gridDim.x * blockDim.x) {
        int col = (int)(i & 1023);
        if (col >= slice) s -= (double)log2f(g_Z[i]);
    }
    __shared__ double sm[256];
    sm[threadIdx.x] = s;
    __syncthreads();
    for (int o = 128; o > 0; o >>= 1) {
        if (threadIdx.x < (unsigned)o) sm[threadIdx.x] += sm[threadIdx.x + o];
        __syncthreads();
    }
    if (threadIdx.x == 0) {
        if (which) g_bp2[blockIdx.x] = sm[0];
        else       g_bp1[blockIdx.x] = sm[0];
    }
}

__global__ void final_k(float* __restrict__ out, const int* __restrict__ slice_ptr) {
    double s = 0.0;
    for (int i = 0; i < 1024; ++i) s += g_bp1[i] + g_bp2[i];
    int slice = slice_ptr ? slice_ptr[0] : 0;
    out[(size_t)2 * BATCH * HS] = (float)(s + 32.0 * (double)slice * (double)BATCH);
}

extern "C" void kernel_launch(void* const* d_in, const int* in_sizes, int n_in,
                              void* d_out, int out_size) {
    (void)in_sizes; (void)out_size;
    const float* x      = (const float*)d_in[0];
    const int*   hidden = (const int*)d_in[1];
    const float* Wzr1   = (const float*)d_in[2];
    const float* bzr1   = (const float*)d_in[3];
    const float* Wg1    = (const float*)d_in[4];
    const float* bg1    = (const float*)d_in[5];
    const float* Wzr2   = (const float*)d_in[6];
    const float* bzr2   = (const float*)d_in[7];
    const float* Wg2    = (const float*)d_in[8];
    const float* bg2    = (const float*)d_in[9];
    const int*   slice  = (n_in > 10) ? (const int*)d_in[10] : nullptr;
    float* out = (float*)d_out;

    // HA = h2_fl
    prep_k<<<4096, 256>>>(hidden);

    // zr1: [x | HA] @ W_zr1 -> z1 (g_Z), HB = r1 * HA
    gemm_k<0><<<dim3(16, 64), 256>>>(x, Wzr1, bzr1, 2048, 0, nullptr, 0, nullptr, 0);
    // bits from z1 (respects slice_dim)
    bits_k<<<1024, 256>>>(slice, 0);

    // g1: [x | HB] @ W_g1 -> h1 update; writes rec/out cols [0,1024), HA = h1_fl
    gemm_k<1><<<dim3(8, 64), 256>>>(x, Wg1, bg1, 1024, 1, hidden, 0, out, 1);

    // zr2: [x | HA(h1_fl)] @ W_zr2 -> z2 (g_Z), HB = r2 * h1_fl
    gemm_k<0><<<dim3(16, 64), 256>>>(x, Wzr2, bzr2, 2048, 0, nullptr, 0, nullptr, 0);
    // bits from z2 (all columns)
    bits_k<<<1024, 256>>>(nullptr, 1);

    // g2: [x | HB] @ W_g2 -> h2 update; writes rec/out cols [1024,2048)
    gemm_k<1><<<dim3(8, 64), 256>>>(x, Wg2, bg2, 1024, 1, hidden, 1024, out, 0);

    // bits scalar
    final_k<<<1, 1>>>(out, slice);
}

// round 3
// speedup vs baseline: 2.5570x; 2.5570x over previous
#include <cuda_runtime.h>
#include <cstdint>

// tcgen05 is only legal in arch-specific ("a") compilation passes.
#if defined(__CUDA_ARCH_FEAT_SM103_ALL) || defined(__CUDA_ARCH_FEAT_SM100_ALL) || defined(__CUDA_ARCH_FEAT_SM101_ALL)
#define HAS_TC 1
#else
#define HAS_TC 0
#endif

typedef long long ll;

#define BATCH 8192
#define INS   1024
#define GG    1024
#define HS    2048
#define KTOT  2048

#define BM 128
#define BN 256
#define BK 32
#define NKI (KTOT/BK)     // 64 K-stages
#define STAGES 4

#define A_BYTES (BM*BK*4)     // 16384
#define B_BYTES (BN*BK*4)     // 32768
#define SM_TMEM 0
#define SM_MBAR 16            // 4 x 8B mbarriers
#define A_OFF  1024
#define B_OFF  (A_OFF + STAGES*A_BYTES)
#define SMEM_TOTAL (B_OFF + STAGES*B_BYTES)   // 197632

// tf32 idesc: dtype=f32(1<<4), atype=btype=tf32(2), N>>3 @17, M>>4 @24
#define IDESC ((1u<<4)|(2u<<7)|(2u<<10)|((BN/8u)<<17)|((BM/16u)<<24))

#define SW(o) ((o) ^ (((o)>>3)&0x70))

static __device__ __forceinline__ uint64_t make_desc(uint32_t addr) {
    return ((uint64_t)2 << 61) | ((uint64_t)1 << 46) | ((uint64_t)64 << 32)
         | ((uint64_t)1 << 16) | ((uint64_t)(addr >> 4) & 0x3FFF);
}

// ---------------- scratch ----------------
__device__ float g_HA[(size_t)BATCH * GG];   // h2_fl, later h1_fl
__device__ float g_HB[(size_t)BATCH * GG];   // r * h_fl
__device__ float g_Z [(size_t)BATCH * GG];   // z1, later z2
__device__ float g_WT[(size_t)KTOT * HS];    // transposed weight [N][K]
__device__ double g_bp1[1024];
__device__ double g_bp2[1024];

// ---------------- helpers ----------------
__device__ __forceinline__ uint32_t smaddr(const void* p) {
    return (uint32_t)__cvta_generic_to_shared(p);
}
__device__ __forceinline__ void cp16(uint32_t d, const void* s) {
    asm volatile("cp.async.cg.shared.global [%0], [%1], 16;\n" :: "r"(d), "l"(s));
}
__device__ __forceinline__ void cpcommit() { asm volatile("cp.async.commit_group;\n" ::); }
template<int N> __device__ __forceinline__ void cpwait() {
    asm volatile("cp.async.wait_group %0;\n" :: "n"(N));
}

#if HAS_TC
__device__ __forceinline__ uint32_t elect_one() {
    uint32_t p;
    asm volatile("{\n\t.reg .pred p;\n\telect.sync _|p, 0xFFFFFFFF;\n\t"
                 "selp.b32 %0, 1, 0, p;\n\t}" : "=r"(p));
    return p;
}
__device__ __forceinline__ void mbar_init(uint32_t mb, uint32_t cnt) {
    asm volatile("mbarrier.init.shared.b64 [%0], %1;" :: "r"(mb), "r"(cnt) : "memory");
}
__device__ __forceinline__ void mbar_inval(uint32_t mb) {
    asm volatile("mbarrier.inval.shared.b64 [%0];" :: "r"(mb) : "memory");
}
__device__ __forceinline__ void mbar_wait(uint32_t mb, uint32_t parity) {
    asm volatile(
        "{\n\t.reg .pred P;\n\t"
        "WL_%=:\n\t"
        "mbarrier.try_wait.parity.acquire.cta.shared::cta.b64 P, [%0], %1, 0x989680;\n\t"
        "@P bra.uni WD_%=;\n\t"
        "bra.uni WL_%=;\n\t"
        "WD_%=:\n\t}"
        :: "r"(mb), "r"(parity) : "memory");
}
__device__ __forceinline__ void tc_alloc(uint32_t smem_slot, uint32_t ncols) {
    asm volatile("tcgen05.alloc.cta_group::1.sync.aligned.shared::cta.b32 [%0], %1;"
                 :: "r"(smem_slot), "r"(ncols) : "memory");
}
__device__ __forceinline__ void tc_dealloc(uint32_t tmem, uint32_t ncols) {
    asm volatile("tcgen05.dealloc.cta_group::1.sync.aligned.b32 %0, %1;" :: "r"(tmem), "r"(ncols));
}
__device__ __forceinline__ void tc_relinq() {
    asm volatile("tcgen05.relinquish_alloc_permit.cta_group::1.sync.aligned;");
}
__device__ __forceinline__ void tc_commit(uint32_t mb) {
    asm volatile("tcgen05.commit.cta_group::1.mbarrier::arrive::one.shared::cluster.b64 [%0];"
                 :: "r"(mb) : "memory");
}
__device__ __forceinline__ void fence_async() {
    asm volatile("fence.proxy.async.shared::cta;" ::: "memory");
}
__device__ __forceinline__ void tc_fence_after() {
    asm volatile("tcgen05.fence::after_thread_sync;" ::: "memory");
}
__device__ __forceinline__ void mma_tf32_ss(uint32_t d, uint64_t a, uint64_t b,
                                            uint32_t idesc, uint32_t en) {
    asm volatile(
        "{\n\t.reg .pred p;\n\tsetp.ne.u32 p, %4, 0;\n\t"
        "tcgen05.mma.cta_group::1.kind::tf32 [%0], %1, %2, %3, {%5, %5, %5, %5}, p;\n\t}"
        :: "r"(d), "l"(a), "l"(b), "r"(idesc), "r"(en), "r"(0u) : "memory");
}
__device__ __forceinline__ void ldtm32(uint32_t* r, uint32_t addr) {
    asm volatile(
        "tcgen05.ld.sync.aligned.32x32b.x32.b32 "
        "{%0,%1,%2,%3,%4,%5,%6,%7,%8,%9,%10,%11,%12,%13,%14,%15,"
        "%16,%17,%18,%19,%20,%21,%22,%23,%24,%25,%26,%27,%28,%29,%30,%31}, [%32];"
        : "=r"(r[0]), "=r"(r[1]), "=r"(r[2]), "=r"(r[3]), "=r"(r[4]), "=r"(r[5]),
          "=r"(r[6]), "=r"(r[7]), "=r"(r[8]), "=r"(r[9]), "=r"(r[10]), "=r"(r[11]),
          "=r"(r[12]), "=r"(r[13]), "=r"(r[14]), "=r"(r[15]), "=r"(r[16]), "=r"(r[17]),
          "=r"(r[18]), "=r"(r[19]), "=r"(r[20]), "=r"(r[21]), "=r"(r[22]), "=r"(r[23]),
          "=r"(r[24]), "=r"(r[25]), "=r"(r[26]), "=r"(r[27]), "=r"(r[28]), "=r"(r[29]),
          "=r"(r[30]), "=r"(r[31])
        : "r"(addr));
}
__device__ __forceinline__ void tc_wait_ld() {
    asm volatile("tcgen05.wait::ld.sync.aligned;" ::: "memory");
}
#else
// legacy m16n8k8 tf32 mma (sm_80+, valid on base sm_103 target)
__device__ __forceinline__ void mma_tf32(float* d, const uint32_t* a, const uint32_t* b) {
    asm volatile(
        "mma.sync.aligned.m16n8k8.row.col.f32.tf32.tf32.f32 "
        "{%0,%1,%2,%3}, {%4,%5,%6,%7}, {%8,%9}, {%0,%1,%2,%3};\n"
        : "+f"(d[0]), "+f"(d[1]), "+f"(d[2]), "+f"(d[3])
        : "r"(a[0]), "r"(a[1]), "r"(a[2]), "r"(a[3]), "r"(b[0]), "r"(b[1]));
}
#endif

__device__ __forceinline__ float sigf(float v) { return 1.0f / (1.0f + expf(-v)); }
__device__ __forceinline__ void hupd(float pre, float z, int h, float* rec, float* oh) {
    float gv = tanhf(pre);
    ll zf = (ll)(z * 1024.0f); if (zf < 1) zf = 1;
    int hi = (int)((((ll)h * zf) >> 10) + (ll)((1.0f - z) * gv * 8388608.0f));
    *rec = (float)hi; *oh = (float)hi * (1.0f / 8388608.0f);
}

// ---------------- GEMM with fused epilogue ----------------
// EPI 0: zr GEMM. cols<1024: z=0.875*sig+0.125 -> g_Z; cols>=1024: g_HB = sig*g_HA
// EPI 1: g GEMM. tanh + fixed-point hidden update, writes rec/out (+ g_HA).
template<int EPI>
__global__ void __launch_bounds__(256, 1) gemm_tc(
    const float* __restrict__ x,
    const float* __restrict__ bias,
    int hinSel,
    const int* __restrict__ hidden,
    int hoff,
    float* __restrict__ out,
    int writeHA)
{
    extern __shared__ char smem[];
    const uint32_t sbase = smaddr(smem);
    const int tid  = threadIdx.x;
    const int wid  = tid >> 5, lane = tid & 31;
    const int bm0  = blockIdx.y * BM;
    const int bn0  = blockIdx.x * BN;
    const float* Hin = hinSel ? g_HB : g_HA;

#if HAS_TC
    if (tid == 0) {
        #pragma unroll
        for (int i = 0; i < 4; ++i) mbar_init(sbase + SM_MBAR + 8 * i, 1);
    }
    if (wid == 0) tc_alloc(sbase + SM_TMEM, 256);
    __syncthreads();
    uint32_t tmem_base;
    asm volatile("ld.shared.b32 %0, [%1];" : "=r"(tmem_base) : "r"(sbase + SM_TMEM));
#endif

    auto load_stage = [&](int kt, int buf) {
        const int kbase = kt * BK;
        const float* asrc = (kbase < INS) ? (x + kbase) : (Hin + (kbase - INS));
        const uint32_t abase = sbase + A_OFF + buf * A_BYTES;
        #pragma unroll
        for (int i = 0; i < 4; ++i) {
            int q = tid + i * 256;
            int row = q >> 3, kc = q & 7;
            uint32_t off = row * 128 + kc * 16;
            cp16(abase + SW(off), asrc + (size_t)(bm0 + row) * INS + kc * 4);
        }
        const uint32_t bbase = sbase + B_OFF + buf * B_BYTES;
        #pragma unroll
        for (int i = 0; i < 8; ++i) {
            int q = tid + i * 256;
            int row = q >> 3, kc = q & 7;
            uint32_t off = row * 128 + kc * 16;
            cp16(bbase + SW(off), g_WT + (size_t)(bn0 + row) * KTOT + kbase + kc * 4);
        }
    };

    #pragma unroll
    for (int s = 0; s < STAGES - 1; ++s) { load_stage(s, s); cpcommit(); }

#if !HAS_TC
    // fallback state: 8 warps as 2(M) x 4(N); warp tile 64x64; m16n8k8 frags
    const int wm0 = (wid >> 2) * 64;
    const int wn0 = (wid & 3) * 64;
    const int rm = lane >> 2, ck = lane & 3;
    float acc[4][8][4];
    #pragma unroll
    for (int i = 0; i < 4; ++i)
        #pragma unroll
        for (int j = 0; j < 8; ++j)
            #pragma unroll
            for (int e = 0; e < 4; ++e) acc[i][j][e] = 0.0f;
#endif

    for (int kt = 0; kt < NKI; ++kt) {
        const int buf = kt & (STAGES - 1);
#if HAS_TC
        if (kt >= 1) mbar_wait(sbase + SM_MBAR + 8 * ((kt - 1) & 3), ((kt - 1) >> 2) & 1);
        const int lt = kt + STAGES - 1;
        if (lt < NKI) load_stage(lt, lt & (STAGES - 1));
        cpcommit();
        cpwait<STAGES - 1>();
        __syncthreads();
        if (wid == 0) {
            fence_async();
            if (elect_one()) {
                uint64_t ad = make_desc(sbase + A_OFF + buf * A_BYTES);
                uint64_t bd = make_desc(sbase + B_OFF + buf * B_BYTES);
                #pragma unroll
                for (int s = 0; s < 4; ++s)
                    mma_tf32_ss(tmem_base, ad + s * 2, bd + s * 2, IDESC,
                                (kt > 0 || s > 0) ? 1u : 0u);
                tc_commit(sbase + SM_MBAR + 8 * (kt & 3));
            }
        }
#else
        const int lt = kt + STAGES - 1;
        if (lt < NKI) load_stage(lt, lt & (STAGES - 1));
        cpcommit();
        cpwait<STAGES - 1>();
        __syncthreads();

        const uint32_t abase = sbase + A_OFF + buf * A_BYTES;  // unused; offsets below
        (void)abase;
        const char* At = smem + A_OFF + buf * A_BYTES;
        const char* Bt = smem + B_OFF + buf * B_BYTES;
        #pragma unroll
        for (int ks = 0; ks < 4; ++ks) {
            const int k0 = ks * 8;
            uint32_t af[4][4];
            #pragma unroll
            for (int mi = 0; mi < 4; ++mi) {
                int m1 = wm0 + mi * 16 + rm;
                int m2 = m1 + 8;
                uint32_t o;
                o = m1 * 128 + (((k0 + ck) * 4)     ^ ((m1 & 7) << 4));
                af[mi][0] = *(const uint32_t*)(At + o);
                o = m2 * 128 + (((k0 + ck) * 4)     ^ ((m2 & 7) << 4));
                af[mi][1] = *(const uint32_t*)(At + o);
                o = m1 * 128 + (((k0 + ck + 4) * 4) ^ ((m1 & 7) << 4));
                af[mi][2] = *(const uint32_t*)(At + o);
                o = m2 * 128 + (((k0 + ck + 4) * 4) ^ ((m2 & 7) << 4));
                af[mi][3] = *(const uint32_t*)(At + o);
            }
            #pragma unroll
            for (int ni = 0; ni < 8; ++ni) {
                int n = wn0 + ni * 8 + rm;
                uint32_t bf[2], o;
                o = n * 128 + (((k0 + ck) * 4)     ^ ((n & 7) << 4));
                bf[0] = *(const uint32_t*)(Bt + o);
                o = n * 128 + (((k0 + ck + 4) * 4) ^ ((n & 7) << 4));
                bf[1] = *(const uint32_t*)(Bt + o);
                #pragma unroll
                for (int mi = 0; mi < 4; ++mi)
                    mma_tf32(acc[mi][ni], af[mi], bf);
            }
        }
        __syncthreads();
#endif
    }

    // ---------------- epilogue ----------------
#if HAS_TC
    mbar_wait(sbase + SM_MBAR + 8 * ((NKI - 1) & 3), ((NKI - 1) >> 2) & 1);
    tc_fence_after();

    const int m = bm0 + (wid & 3) * 32 + lane;
    const int cb0 = (wid >> 2) * 128;

    #pragma unroll
    for (int ch = 0; ch < 4; ++ch) {
        const int nb = cb0 + ch * 32;
        uint32_t r[32];
        ldtm32(r, tmem_base + nb);
        tc_wait_ld();
        const int n0 = bn0 + nb;

        if (EPI == 0) {
            if (n0 < GG) {
                #pragma unroll
                for (int c = 0; c < 32; c += 4) {
                    float4 bv = *(const float4*)&bias[n0 + c];
                    float4 zv;
                    zv.x = 0.875f * sigf(__uint_as_float(r[c + 0]) + bv.x) + 0.125f;
                    zv.y = 0.875f * sigf(__uint_as_float(r[c + 1]) + bv.y) + 0.125f;
                    zv.z = 0.875f * sigf(__uint_as_float(r[c + 2]) + bv.z) + 0.125f;
                    zv.w = 0.875f * sigf(__uint_as_float(r[c + 3]) + bv.w) + 0.125f;
                    *(float4*)&g_Z[(size_t)m * GG + n0 + c] = zv;
                }
            } else {
                #pragma unroll
                for (int c = 0; c < 32; c += 4) {
                    float4 bv = *(const float4*)&bias[n0 + c];
                    size_t j = (size_t)m * GG + (n0 - GG) + c;
                    float4 ha = *(const float4*)&g_HA[j];
                    float4 hb;
                    hb.x = ha.x * sigf(__uint_as_float(r[c + 0]) + bv.x);
                    hb.y = ha.y * sigf(__uint_as_float(r[c + 1]) + bv.y);
                    hb.z = ha.z * sigf(__uint_as_float(r[c + 2]) + bv.z);
                    hb.w = ha.w * sigf(__uint_as_float(r[c + 3]) + bv.w);
                    *(float4*)&g_HB[j] = hb;
                }
            }
        } else {
            #pragma unroll
            for (int c = 0; c < 32; c += 4) {
                float4 bv = *(const float4*)&bias[n0 + c];
                size_t zj = (size_t)m * GG + n0 + c;
                float4 zv = *(const float4*)&g_Z[zj];
                int4 hv = *(const int4*)&hidden[(size_t)m * HS + hoff + n0 + c];
                float4 recf, ohf;
                hupd(__uint_as_float(r[c + 0]) + bv.x, zv.x, hv.x, &recf.x, &ohf.x);
                hupd(__uint_as_float(r[c + 1]) + bv.y, zv.y, hv.y, &recf.y, &ohf.y);
                hupd(__uint_as_float(r[c + 2]) + bv.z, zv.z, hv.z, &recf.z, &ohf.z);
                hupd(__uint_as_float(r[c + 3]) + bv.w, zv.w, hv.w, &recf.w, &ohf.w);
                *(float4*)&out[(size_t)m * HS + hoff + n0 + c] = recf;
                *(float4*)&out[(size_t)BATCH * HS + (size_t)m * HS + hoff + n0 + c] = ohf;
                if (writeHA) *(float4*)&g_HA[zj] = ohf;
            }
        }
    }

    __syncthreads();
    if (tid == 0) {
        #pragma unroll
        for (int i = 0; i < 4; ++i) mbar_inval(sbase + SM_MBAR + 8 * i);
    }
    __syncthreads();
    if (wid == 0) { tc_relinq(); tc_dealloc(tmem_base, 256); }
#else
    const int c2 = (lane & 3) * 2;
    #pragma unroll
    for (int mi = 0; mi < 4; ++mi) {
        #pragma unroll
        for (int rr = 0; rr < 2; ++rr) {
            int m = bm0 + wm0 + mi * 16 + rm + rr * 8;
            #pragma unroll
            for (int ni = 0; ni < 8; ++ni) {
                int n = bn0 + wn0 + ni * 8 + c2;
                float p0 = acc[mi][ni][rr * 2 + 0] + bias[n];
                float p1 = acc[mi][ni][rr * 2 + 1] + bias[n + 1];
                if (EPI == 0) {
                    float s0 = sigf(p0), s1 = sigf(p1);
                    if (n < GG) {
                        float2 z; z.x = 0.875f * s0 + 0.125f; z.y = 0.875f * s1 + 0.125f;
                        *(float2*)&g_Z[(size_t)m * GG + n] = z;
                    } else {
                        size_t j = (size_t)m * GG + (n - GG);
                        float2 ha = *(const float2*)&g_HA[j];
                        float2 hb; hb.x = s0 * ha.x; hb.y = s1 * ha.y;
                        *(float2*)&g_HB[j] = hb;
                    }
                } else {
                    size_t zj = (size_t)m * GG + n;
                    float2 zv = *(const float2*)&g_Z[zj];
                    int2 hv = *(const int2*)&hidden[(size_t)m * HS + hoff + n];
                    float2 recf, ohf;
                    hupd(p0, zv.x, hv.x, &recf.x, &ohf.x);
                    hupd(p1, zv.y, hv.y, &recf.y, &ohf.y);
                    *(float2*)&out[(size_t)m * HS + hoff + n] = recf;
                    *(float2*)&out[(size_t)BATCH * HS + (size_t)m * HS + hoff + n] = ohf;
                    if (writeHA) *(float2*)&g_HA[zj] = ohf;
                }
            }
        }
    }
#endif
}

// ---------------- aux kernels ----------------
__global__ void transpose_k(const float* __restrict__ W, int N) {
    __shared__ float t[32][33];
    int n0 = blockIdx.x * 32, k0 = blockIdx.y * 32;
    int tx = threadIdx.x, ty = threadIdx.y;   // 32 x 8
    #pragma unroll
    for (int i = 0; i < 32; i += 8)
        t[ty + i][tx] = W[(size_t)(k0 + ty + i) * N + n0 + tx];
    __syncthreads();
    #pragma unroll
    for (int i = 0; i < 32; i += 8)
        g_WT[(size_t)(n0 + ty + i) * KTOT + k0 + tx] = t[tx][ty + i];
}

__global__ void prep_k(const int* __restrict__ hidden) {
    size_t N = (size_t)BATCH * GG;
    for (size_t i = (size_t)blockIdx.x * blockDim.x + threadIdx.x; i < N;
         i += (size_t)gridDim.x * blockDim.x) {
        size_t row = i >> 10;
        int col = (int)(i & 1023);
        g_HA[i] = (float)hidden[row * HS + GG + col] * (1.0f / 8388608.0f);
    }
}

__global__ void bits_k(const int* __restrict__ slice_ptr, int which) {
    int slice = slice_ptr ? __ldg(slice_ptr) : 0;
    double s = 0.0;
    size_t N = (size_t)BATCH * GG;
    for (size_t i = (size_t)blockIdx.x * blockDim.x + threadIdx.x; i < N;
         i += (size_t)gridDim.x * blockDim.x) {
        int col = (int)(i & 1023);
        if (col >= slice) s -= (double)log2f(g_Z[i]);
    }
    __shared__ double sm[256];
    sm[threadIdx.x] = s;
    __syncthreads();
    for (int o = 128; o > 0; o >>= 1) {
        if (threadIdx.x < (unsigned)o) sm[threadIdx.x] += sm[threadIdx.x + o];
        __syncthreads();
    }
    if (threadIdx.x == 0) {
        if (which) g_bp2[blockIdx.x] = sm[0];
        else       g_bp1[blockIdx.x] = sm[0];
    }
}

__global__ void final_k(float* __restrict__ out, const int* __restrict__ slice_ptr) {
    double s = 0.0;
    for (int i = 0; i < 1024; ++i) s += g_bp1[i] + g_bp2[i];
    int slice = slice_ptr ? slice_ptr[0] : 0;
    out[(size_t)2 * BATCH * HS] = (float)(s + 32.0 * (double)slice * (double)BATCH);
}

extern "C" void kernel_launch(void* const* d_in, const int* in_sizes, int n_in,
                              void* d_out, int out_size) {
    (void)in_sizes; (void)out_size;
    const float* x      = (const float*)d_in[0];
    const int*   hidden = (const int*)d_in[1];
    const float* Wzr1   = (const float*)d_in[2];
    const float* bzr1   = (const float*)d_in[3];
    const float* Wg1    = (const float*)d_in[4];
    const float* bg1    = (const float*)d_in[5];
    const float* Wzr2   = (const float*)d_in[6];
    const float* bzr2   = (const float*)d_in[7];
    const float* Wg2    = (const float*)d_in[8];
    const float* bg2    = (const float*)d_in[9];
    const int*   slice  = (n_in > 10) ? (const int*)d_in[10] : nullptr;
    float* out = (float*)d_out;

    cudaFuncSetAttribute(gemm_tc<0>, cudaFuncAttributeMaxDynamicSharedMemorySize, SMEM_TOTAL);
    cudaFuncSetAttribute(gemm_tc<1>, cudaFuncAttributeMaxDynamicSharedMemorySize, SMEM_TOTAL);

    prep_k<<<4096, 256>>>(hidden);

    // zr1
    transpose_k<<<dim3(64, 64), dim3(32, 8)>>>(Wzr1, HS);
    gemm_tc<0><<<dim3(HS / BN, BATCH / BM), 256, SMEM_TOTAL>>>(x, bzr1, 0, nullptr, 0, nullptr, 0);
    bits_k<<<1024, 256>>>(slice, 0);

    // g1
    transpose_k<<<dim3(32, 64), dim3(32, 8)>>>(Wg1, GG);
    gemm_tc<1><<<dim3(GG / BN, BATCH / BM), 256, SMEM_TOTAL>>>(x, bg1, 1, hidden, 0, out, 1);

    // zr2
    transpose_k<<<dim3(64, 64), dim3(32, 8)>>>(Wzr2, HS);
    gemm_tc<0><<<dim3(HS / BN, BATCH / BM), 256, SMEM_TOTAL>>>(x, bzr2, 0, nullptr, 0, nullptr, 0);
    bits_k<<<1024, 256>>>(nullptr, 1);

    // g2
    transpose_k<<<dim3(32, 64), dim3(32, 8)>>>(Wg2, GG);
    gemm_tc<1><<<dim3(GG / BN, BATCH / BM), 256, SMEM_TOTAL>>>(x, bg2, 1, hidden, 1024, out, 0);

    final_k<<<1, 1>>>(out, slice);
}